// round 9
// baseline (speedup 1.0000x reference)
#include <cuda_runtime.h>
#include <math.h>
#include <stdint.h>

// Problem constants
#define BS 16
#define L  8192
#define D  512
#define NROWS (BS * L)          // 131072 timestep-rows
#define CHUNK 128               // timesteps per chunk
#define NCHUNKS (NROWS / CHUNK) // 1024
#define CPR (L / CHUNK)         // 64 chunks per batch row
#define TAU 2.0f
#define NEG -10000.0f
#define FN_ID 0xE4u             // identity fn: 0,1,2,3 -> 0,1,2,3

#define GEMV_BLOCKS 1184        // 8 * 148 SMs
#define DEPTH 3                 // per-warp pipeline stages

// Scratch (device globals — no allocation). SoA logits for coalesced access.
__device__ float g_l0[NROWS];
__device__ float g_l1[NROWS];
// decoupled-lookback flag words: 0 = not ready, else 0x100 | chunk_fn
__device__ unsigned g_flagword[NCHUNKS];

// fn: {0..3}->{0..3} packed 2 bits/entry. compose(first, second)(s) = second(first(s))
__device__ __forceinline__ unsigned compose_fn(unsigned first, unsigned second) {
    unsigned r = 0;
#pragma unroll
    for (int s = 0; s < 4; s++) {
        unsigned fs = (first >> (2 * s)) & 3u;
        r |= ((second >> (2 * fs)) & 3u) << (2 * s);
    }
    return r;
}

__device__ __forceinline__ unsigned step_fn(float l0, float l1) {
    unsigned u = (l1 > l0) ? 1u : 0u;           // decision if flag==0
    unsigned m = ((l1 + NEG) > l0) ? 1u : 0u;   // decision if flag>0
    unsigned e0 = u ? 3u : 0u;
    unsigned e1 = m ? 3u : 0u;
    unsigned e2 = m ? 3u : 1u;
    unsigned e3 = m ? 3u : 2u;
    return e0 | (e1 << 2) | (e2 << 4) | (e3 << 6);
}

__device__ __forceinline__ void publish_word(unsigned* p, unsigned v) {
    asm volatile("st.release.gpu.global.b32 [%0], %1;\n" :: "l"(p), "r"(v) : "memory");
}
__device__ __forceinline__ unsigned poll_word(const unsigned* p) {
    unsigned v;
    do {
        asm volatile("ld.acquire.gpu.global.b32 %0, [%1];\n" : "=r"(v) : "l"(p) : "memory");
    } while (v == 0u);
    return v & 0xFFu;
}

// Issue one row (128 float4) into a warp stage. Lane loads exactly the four
// float4s it will later read back — self-synchronized by per-thread cp.async
// groups; no barriers.
__device__ __forceinline__ void fill_row(float4* dst, const float4* src,
                                         int lane, bool valid)
{
    if (valid) {
#pragma unroll
        for (int k = 0; k < 4; k++) {
            uint32_t s = (uint32_t)__cvta_generic_to_shared(dst + lane + 32 * k);
            const float4* g = src + lane + 32 * k;
            asm volatile("cp.async.cg.shared.global [%0], [%1], 16;\n"
                         :: "r"(s), "l"(g) : "memory");
        }
    }
    asm volatile("cp.async.commit_group;\n" ::: "memory");  // uniform accounting
}

// ---------------------------------------------------------------------------
// Kernel 1: GEMV. Warp-autonomous 3-stage cp.async pipeline, one row/stage.
// Also zeroes the lookback flag words (one per block).
// ---------------------------------------------------------------------------
__global__ void __launch_bounds__(256) gemv_kernel(
    const float* __restrict__ x,
    const float* __restrict__ W,
    const float* __restrict__ bias)
{
    __shared__ float4 stage[8][DEPTH][128];     // 8 warps x 3 x 2KB = 48KB
    __shared__ float sW[D * 2];

    const int tid  = threadIdx.x;
    const int lane = tid & 31;
    const int warp = tid >> 5;

    if (tid == 0 && blockIdx.x < NCHUNKS) g_flagword[blockIdx.x] = 0u;

    for (int i = tid; i < D * 2; i += 256) sW[i] = W[i];
    __syncthreads();

    // per-lane W slice: d = lane*4 + k*128 + j
    float w0[16], w1[16];
#pragma unroll
    for (int k = 0; k < 4; k++)
#pragma unroll
        for (int j = 0; j < 4; j++) {
            int d = lane * 4 + k * 128 + j;
            w0[k * 4 + j] = sW[d * 2 + 0];
            w1[k * 4 + j] = sW[d * 2 + 1];
        }
    const float b0 = bias[0], b1 = bias[1];

    const float4* x4 = reinterpret_cast<const float4*>(x);
    const int gwarp  = blockIdx.x * 8 + warp;
    const int nwarps = GEMV_BLOCKS * 8;         // 9472

    float4* const st = &stage[warp][0][0];

    // prime DEPTH stages
    int rfill = gwarp;
#pragma unroll
    for (int s = 0; s < DEPTH; s++) {
        fill_row(st + s * 128, x4 + (size_t)rfill * 128, lane, rfill < NROWS);
        rfill += nwarps;
    }

    int s = 0;
#pragma unroll 1
    for (int row = gwarp; row < NROWS; row += nwarps) {
        asm volatile("cp.async.wait_group %0;\n" :: "n"(DEPTH - 1) : "memory");

        const float4* rp = st + s * 128;
        float4 v0 = rp[lane +  0];
        float4 v1 = rp[lane + 32];
        float4 v2 = rp[lane + 64];
        float4 v3 = rp[lane + 96];

        fill_row(st + s * 128, x4 + (size_t)rfill * 128, lane, rfill < NROWS);
        rfill += nwarps;
        s = (s + 1 == DEPTH) ? 0 : s + 1;

        float a0 = 0.f, a1 = 0.f;
        a0 = fmaf(v0.x, w0[0],  a0); a1 = fmaf(v0.x, w1[0],  a1);
        a0 = fmaf(v0.y, w0[1],  a0); a1 = fmaf(v0.y, w1[1],  a1);
        a0 = fmaf(v0.z, w0[2],  a0); a1 = fmaf(v0.z, w1[2],  a1);
        a0 = fmaf(v0.w, w0[3],  a0); a1 = fmaf(v0.w, w1[3],  a1);
        a0 = fmaf(v1.x, w0[4],  a0); a1 = fmaf(v1.x, w1[4],  a1);
        a0 = fmaf(v1.y, w0[5],  a0); a1 = fmaf(v1.y, w1[5],  a1);
        a0 = fmaf(v1.z, w0[6],  a0); a1 = fmaf(v1.z, w1[6],  a1);
        a0 = fmaf(v1.w, w0[7],  a0); a1 = fmaf(v1.w, w1[7],  a1);
        a0 = fmaf(v2.x, w0[8],  a0); a1 = fmaf(v2.x, w1[8],  a1);
        a0 = fmaf(v2.y, w0[9],  a0); a1 = fmaf(v2.y, w1[9],  a1);
        a0 = fmaf(v2.z, w0[10], a0); a1 = fmaf(v2.z, w1[10], a1);
        a0 = fmaf(v2.w, w0[11], a0); a1 = fmaf(v2.w, w1[11], a1);
        a0 = fmaf(v3.x, w0[12], a0); a1 = fmaf(v3.x, w1[12], a1);
        a0 = fmaf(v3.y, w0[13], a0); a1 = fmaf(v3.y, w1[13], a1);
        a0 = fmaf(v3.z, w0[14], a0); a1 = fmaf(v3.z, w1[14], a1);
        a0 = fmaf(v3.w, w0[15], a0); a1 = fmaf(v3.w, w1[15], a1);

        // combined dual reduction: 6 shfls
        a0 += __shfl_xor_sync(0xffffffffu, a0, 16);
        a1 += __shfl_xor_sync(0xffffffffu, a1, 16);
        float r = (lane < 16) ? a0 : a1;
#pragma unroll
        for (int off = 8; off > 0; off >>= 1)
            r += __shfl_xor_sync(0xffffffffu, r, off);

        if (lane == 0)  g_l0[row] = r + b0;
        if (lane == 16) g_l1[row] = r + b1;
    }
}

// ---------------------------------------------------------------------------
// Kernel 2 (fused): replay with decoupled lookback (aggregates only).
// 1024 blocks x 128 threads — all resident in one wave, so spin-wait is safe.
// ---------------------------------------------------------------------------
__global__ void __launch_bounds__(128) replay_kernel(float* __restrict__ out)
{
    const int blk  = blockIdx.x;
    const int row  = blk / CPR;
    const int c    = blk % CPR;
    const int t    = threadIdx.x;
    const int lane = t & 31;
    const int w    = t >> 5;

    __shared__ unsigned sAgg[4];
    __shared__ unsigned s_inflag;

    const size_t base = (size_t)row * L + (size_t)c * CHUNK;

    const float l0 = g_l0[base + t];
    const float l1 = g_l1[base + t];

    // warp inclusive scan of step functions (time order = lane order)
    unsigned incl = step_fn(l0, l1);
#pragma unroll
    for (int off = 1; off < 32; off <<= 1) {
        unsigned p = __shfl_up_sync(0xffffffffu, incl, off);
        if (lane >= off) incl = compose_fn(p, incl);
    }
    if (lane == 31) sAgg[w] = incl;
    __syncthreads();

    // publish this chunk's composed fn (warp order 0..3 = time order)
    if (t == 0) {
        unsigned fn = compose_fn(compose_fn(sAgg[0], sAgg[1]),
                                 compose_fn(sAgg[2], sAgg[3]));
        publish_word(&g_flagword[blk], 0x100u | fn);
    }

    // warp 0: lookback over predecessor chunk fns (poll until published)
    if (w == 0) {
        const unsigned* fw = g_flagword + row * CPR;
        unsigned a = (2 * lane     < c) ? poll_word(fw + 2 * lane)     : FN_ID;
        unsigned b = (2 * lane + 1 < c) ? poll_word(fw + 2 * lane + 1) : FN_ID;
        unsigned v = compose_fn(a, b);
#pragma unroll
        for (int off = 1; off < 32; off <<= 1) {
            unsigned p = __shfl_up_sync(0xffffffffu, v, off);
            if (lane >= off) v = compose_fn(p, v);
        }
        int src = ((c + 1) >> 1) - 1;                 // ceil(c/2)-1 (valid for c>0)
        unsigned F = __shfl_sync(0xffffffffu, v, src < 0 ? 0 : src);
        if (lane == 0) s_inflag = (c == 0) ? 0u : (F & 3u);
    }
    __syncthreads();

    // prefix of preceding warps (<=3 composes, contiguous order)
    unsigned wpre = FN_ID;
#pragma unroll
    for (int ww = 0; ww < 3; ww++)
        if (ww < w) wpre = compose_fn(wpre, sAgg[ww]);

    // exclusive within warp
    unsigned ex = __shfl_up_sync(0xffffffffu, incl, 1);
    if (lane == 0) ex = FN_ID;
    unsigned X = compose_fn(wpre, ex);

    const unsigned inflag = s_inflag;
    unsigned flag = (X >> (2 * inflag)) & 3u;

    float lm1 = (flag > 0u) ? (l1 + NEG) : l1;
    int pred = (lm1 > l0) ? 1 : 0;

    float mx    = fmaxf(l0, lm1);
    float other = pred ? l0 : lm1;
    float g = -log1pf(expf((other - mx) * (1.0f / TAU)));

    out[base + t]                 = (float)pred;
    out[(size_t)NROWS + base + t] = g;
}

// ---------------------------------------------------------------------------
extern "C" void kernel_launch(void* const* d_in, const int* in_sizes, int n_in,
                              void* d_out, int out_size)
{
    const float* x    = (const float*)d_in[0];   // [16, 8192, 512] f32
    // d_in[1] = label (int32) — unused
    const float* W    = (const float*)d_in[2];   // [512, 2] f32
    const float* bias = (const float*)d_in[3];   // [2] f32
    float* out = (float*)d_out;

    gemv_kernel<<<GEMV_BLOCKS, 256>>>(x, W, bias);
    replay_kernel<<<NCHUNKS, 128>>>(out);
}

// round 10
// speedup vs baseline: 1.1887x; 1.1887x over previous
#include <cuda_runtime.h>
#include <math.h>
#include <stdint.h>

// Problem constants
#define BS 16
#define L  8192
#define D  512
#define NROWS (BS * L)          // 131072 timestep-rows
#define CHUNK 256               // timesteps per chunk
#define NCHUNKS (NROWS / CHUNK) // 512
#define CPR (L / CHUNK)         // 32 chunks per batch row
#define TAU 2.0f
#define NEG -10000.0f
#define FN_ID 0xE4u             // identity fn: 0,1,2,3 -> 0,1,2,3

#define GEMV_BLOCKS 1184        // 8 * 148 SMs
#define DEPTH 3                 // per-warp pipeline stages

// Scratch (device globals — no allocation). SoA logits for coalesced access.
__device__ float g_l0[NROWS];
__device__ float g_l1[NROWS];
__device__ unsigned char g_chunkfn[NCHUNKS];

// fn: {0..3}->{0..3} packed 2 bits/entry. compose(first, second)(s) = second(first(s))
__device__ __forceinline__ unsigned compose_fn(unsigned first, unsigned second) {
    unsigned r = 0;
#pragma unroll
    for (int s = 0; s < 4; s++) {
        unsigned fs = (first >> (2 * s)) & 3u;
        r |= ((second >> (2 * fs)) & 3u) << (2 * s);
    }
    return r;
}

__device__ __forceinline__ unsigned step_fn(float l0, float l1) {
    unsigned u = (l1 > l0) ? 1u : 0u;           // decision if flag==0
    unsigned m = ((l1 + NEG) > l0) ? 1u : 0u;   // decision if flag>0
    unsigned e0 = u ? 3u : 0u;
    unsigned e1 = m ? 3u : 0u;
    unsigned e2 = m ? 3u : 1u;
    unsigned e3 = m ? 3u : 2u;
    return e0 | (e1 << 2) | (e2 << 4) | (e3 << 6);
}

// Issue one row (128 float4) into a warp stage. Lane loads exactly the four
// float4s it will later read back — self-synchronized by per-thread cp.async
// groups; no barriers.
__device__ __forceinline__ void fill_row(float4* dst, const float4* src,
                                         int lane, bool valid)
{
    if (valid) {
#pragma unroll
        for (int k = 0; k < 4; k++) {
            uint32_t s = (uint32_t)__cvta_generic_to_shared(dst + lane + 32 * k);
            const float4* g = src + lane + 32 * k;
            asm volatile("cp.async.cg.shared.global [%0], [%1], 16;\n"
                         :: "r"(s), "l"(g) : "memory");
        }
    }
    asm volatile("cp.async.commit_group;\n" ::: "memory");  // uniform accounting
}

// ---------------------------------------------------------------------------
// Kernel 1: GEMV. Warp-autonomous 3-stage cp.async pipeline, one row/stage.
// ---------------------------------------------------------------------------
__global__ void __launch_bounds__(256) gemv_kernel(
    const float* __restrict__ x,
    const float* __restrict__ W,
    const float* __restrict__ bias)
{
    __shared__ float4 stage[8][DEPTH][128];     // 8 warps x 3 x 2KB = 48KB
    __shared__ float sW[D * 2];

    const int tid  = threadIdx.x;
    const int lane = tid & 31;
    const int warp = tid >> 5;

    for (int i = tid; i < D * 2; i += 256) sW[i] = W[i];
    __syncthreads();

    // per-lane W slice: d = lane*4 + k*128 + j
    float w0[16], w1[16];
#pragma unroll
    for (int k = 0; k < 4; k++)
#pragma unroll
        for (int j = 0; j < 4; j++) {
            int d = lane * 4 + k * 128 + j;
            w0[k * 4 + j] = sW[d * 2 + 0];
            w1[k * 4 + j] = sW[d * 2 + 1];
        }
    const float b0 = bias[0], b1 = bias[1];

    const float4* x4 = reinterpret_cast<const float4*>(x);
    const int gwarp  = blockIdx.x * 8 + warp;
    const int nwarps = GEMV_BLOCKS * 8;         // 9472

    float4* const st = &stage[warp][0][0];

    // prime DEPTH stages
    int rfill = gwarp;
#pragma unroll
    for (int s = 0; s < DEPTH; s++) {
        fill_row(st + s * 128, x4 + (size_t)rfill * 128, lane, rfill < NROWS);
        rfill += nwarps;
    }

    int s = 0;
#pragma unroll 1
    for (int row = gwarp; row < NROWS; row += nwarps) {
        asm volatile("cp.async.wait_group %0;\n" :: "n"(DEPTH - 1) : "memory");

        const float4* rp = st + s * 128;
        float4 v0 = rp[lane +  0];
        float4 v1 = rp[lane + 32];
        float4 v2 = rp[lane + 64];
        float4 v3 = rp[lane + 96];

        fill_row(st + s * 128, x4 + (size_t)rfill * 128, lane, rfill < NROWS);
        rfill += nwarps;
        s = (s + 1 == DEPTH) ? 0 : s + 1;

        float a0 = 0.f, a1 = 0.f;
        a0 = fmaf(v0.x, w0[0],  a0); a1 = fmaf(v0.x, w1[0],  a1);
        a0 = fmaf(v0.y, w0[1],  a0); a1 = fmaf(v0.y, w1[1],  a1);
        a0 = fmaf(v0.z, w0[2],  a0); a1 = fmaf(v0.z, w1[2],  a1);
        a0 = fmaf(v0.w, w0[3],  a0); a1 = fmaf(v0.w, w1[3],  a1);
        a0 = fmaf(v1.x, w0[4],  a0); a1 = fmaf(v1.x, w1[4],  a1);
        a0 = fmaf(v1.y, w0[5],  a0); a1 = fmaf(v1.y, w1[5],  a1);
        a0 = fmaf(v1.z, w0[6],  a0); a1 = fmaf(v1.z, w1[6],  a1);
        a0 = fmaf(v1.w, w0[7],  a0); a1 = fmaf(v1.w, w1[7],  a1);
        a0 = fmaf(v2.x, w0[8],  a0); a1 = fmaf(v2.x, w1[8],  a1);
        a0 = fmaf(v2.y, w0[9],  a0); a1 = fmaf(v2.y, w1[9],  a1);
        a0 = fmaf(v2.z, w0[10], a0); a1 = fmaf(v2.z, w1[10], a1);
        a0 = fmaf(v2.w, w0[11], a0); a1 = fmaf(v2.w, w1[11], a1);
        a0 = fmaf(v3.x, w0[12], a0); a1 = fmaf(v3.x, w1[12], a1);
        a0 = fmaf(v3.y, w0[13], a0); a1 = fmaf(v3.y, w1[13], a1);
        a0 = fmaf(v3.z, w0[14], a0); a1 = fmaf(v3.z, w1[14], a1);
        a0 = fmaf(v3.w, w0[15], a0); a1 = fmaf(v3.w, w1[15], a1);

        // combined dual reduction: 6 shfls
        a0 += __shfl_xor_sync(0xffffffffu, a0, 16);
        a1 += __shfl_xor_sync(0xffffffffu, a1, 16);
        float r = (lane < 16) ? a0 : a1;
#pragma unroll
        for (int off = 8; off > 0; off >>= 1)
            r += __shfl_xor_sync(0xffffffffu, r, off);

        if (lane == 0)  g_l0[row] = r + b0;
        if (lane == 16) g_l1[row] = r + b1;
    }
}

// ---------------------------------------------------------------------------
// Kernel 2: per-chunk transition function. One warp per 256-step chunk;
// lane covers 8 consecutive steps. Ordered (contiguous) composition only.
// ---------------------------------------------------------------------------
__global__ void __launch_bounds__(256) chunkfn_kernel()
{
    const int lane  = threadIdx.x & 31;
    const int warp  = threadIdx.x >> 5;
    const int chunk = blockIdx.x * 8 + warp;     // grid = 64 blocks

    const size_t base = (size_t)chunk * CHUNK + (size_t)lane * 8;
    float4 a0 = *reinterpret_cast<const float4*>(g_l0 + base);
    float4 a1 = *reinterpret_cast<const float4*>(g_l0 + base + 4);
    float4 b0 = *reinterpret_cast<const float4*>(g_l1 + base);
    float4 b1 = *reinterpret_cast<const float4*>(g_l1 + base + 4);

    unsigned f = step_fn(a0.x, b0.x);
    f = compose_fn(f, step_fn(a0.y, b0.y));
    f = compose_fn(f, step_fn(a0.z, b0.z));
    f = compose_fn(f, step_fn(a0.w, b0.w));
    f = compose_fn(f, step_fn(a1.x, b1.x));
    f = compose_fn(f, step_fn(a1.y, b1.y));
    f = compose_fn(f, step_fn(a1.z, b1.z));
    f = compose_fn(f, step_fn(a1.w, b1.w));

    // ordered tree reduce (ascending offsets): lane 0 ends with full chunk fn
#pragma unroll
    for (int off = 1; off < 32; off <<= 1) {
        unsigned other = __shfl_down_sync(0xffffffffu, f, off);
        f = compose_fn(f, other);
    }
    if (lane == 0) g_chunkfn[chunk] = (unsigned char)f;
}

// ---------------------------------------------------------------------------
// Kernel 3: replay. 512 blocks x 128 threads; thread handles 2 timesteps
// (float2 IO). Warp scan over per-thread pair-fns; 4-warp aggregate; pair-
// packed lookback over <=31 predecessor chunk fns.
// ---------------------------------------------------------------------------
__global__ void __launch_bounds__(128) replay_kernel(float* __restrict__ out)
{
    const int blk  = blockIdx.x;
    const int row  = blk / CPR;
    const int c    = blk % CPR;
    const int t    = threadIdx.x;
    const int lane = t & 31;
    const int w    = t >> 5;

    __shared__ unsigned sAgg[4];
    __shared__ unsigned s_inflag;

    const size_t base = (size_t)row * L + (size_t)c * CHUNK;

    const float2 l0p = *reinterpret_cast<const float2*>(g_l0 + base + 2 * t);
    const float2 l1p = *reinterpret_cast<const float2*>(g_l1 + base + 2 * t);

    // thread fn = composition of its two steps (time order)
    unsigned incl = compose_fn(step_fn(l0p.x, l1p.x), step_fn(l0p.y, l1p.y));
#pragma unroll
    for (int off = 1; off < 32; off <<= 1) {
        unsigned p = __shfl_up_sync(0xffffffffu, incl, off);
        if (lane >= off) incl = compose_fn(p, incl);
    }
    if (lane == 31) sAgg[w] = incl;

    // warp 0: incoming flag from predecessor chunk fns (<=31)
    if (w == 0) {
        const unsigned char* cf = g_chunkfn + row * CPR;
        unsigned a = (2 * lane     < c) ? (unsigned)cf[2 * lane]     : FN_ID;
        unsigned b = (2 * lane + 1 < c) ? (unsigned)cf[2 * lane + 1] : FN_ID;
        unsigned v = compose_fn(a, b);
#pragma unroll
        for (int off = 1; off < 32; off <<= 1) {
            unsigned p = __shfl_up_sync(0xffffffffu, v, off);
            if (lane >= off) v = compose_fn(p, v);
        }
        int src = ((c + 1) >> 1) - 1;                 // ceil(c/2)-1 (valid for c>0)
        unsigned F = __shfl_sync(0xffffffffu, v, src < 0 ? 0 : src);
        if (lane == 0) s_inflag = (c == 0) ? 0u : (F & 3u);
    }
    __syncthreads();

    // prefix of preceding warps (<=3 composes, contiguous order)
    unsigned wpre = FN_ID;
#pragma unroll
    for (int ww = 0; ww < 3; ww++)
        if (ww < w) wpre = compose_fn(wpre, sAgg[ww]);

    // exclusive within warp (thread granularity)
    unsigned ex = __shfl_up_sync(0xffffffffu, incl, 1);
    if (lane == 0) ex = FN_ID;
    unsigned X = compose_fn(wpre, ex);

    const unsigned inflag = s_inflag;
    unsigned flag = (X >> (2 * inflag)) & 3u;

    // serial replay of this thread's two steps
    float2 ob, og;

    {   // step 0
        float lm1 = (flag > 0u) ? (l1p.x + NEG) : l1p.x;
        int pred = (lm1 > l0p.x) ? 1 : 0;
        flag = (flag > 0u) ? (flag - 1u) : 0u;
        if (pred) flag = 3u;
        float mx    = fmaxf(l0p.x, lm1);
        float other = pred ? l0p.x : lm1;
        ob.x = (float)pred;
        og.x = -log1pf(expf((other - mx) * (1.0f / TAU)));
    }
    {   // step 1
        float lm1 = (flag > 0u) ? (l1p.y + NEG) : l1p.y;
        int pred = (lm1 > l0p.y) ? 1 : 0;
        float mx    = fmaxf(l0p.y, lm1);
        float other = pred ? l0p.y : lm1;
        ob.y = (float)pred;
        og.y = -log1pf(expf((other - mx) * (1.0f / TAU)));
    }

    *reinterpret_cast<float2*>(out + base + 2 * t)                 = ob;
    *reinterpret_cast<float2*>(out + (size_t)NROWS + base + 2 * t) = og;
}

// ---------------------------------------------------------------------------
extern "C" void kernel_launch(void* const* d_in, const int* in_sizes, int n_in,
                              void* d_out, int out_size)
{
    const float* x    = (const float*)d_in[0];   // [16, 8192, 512] f32
    // d_in[1] = label (int32) — unused
    const float* W    = (const float*)d_in[2];   // [512, 2] f32
    const float* bias = (const float*)d_in[3];   // [2] f32
    float* out = (float*)d_out;

    gemv_kernel<<<GEMV_BLOCKS, 256>>>(x, W, bias);
    chunkfn_kernel<<<NCHUNKS / 8, 256>>>();
    replay_kernel<<<NCHUNKS, 128>>>(out);
}